// round 1
// baseline (speedup 1.0000x reference)
#include <cuda_runtime.h>
#include <math.h>

// ---------------------------------------------------------------------------
// Problem constants
// ---------------------------------------------------------------------------
#define BSZ   4
#define LEN   2048
#define DIM   1024
#define NH    8
#define NE    16
#define TOPK  2
#define HD    128          // DIM / NH
#define II    512          // per-expert intermediate
#define NTOK  (BSZ*LEN)    // 8192 tokens
#define NSUB  (NTOK*NH)    // 65536 sub-tokens
#define NPAIR (NSUB*TOPK)  // 131072 (token, expert) pairs

// ---------------------------------------------------------------------------
// Device scratch (static __device__ arrays; no allocation in kernel_launch)
// ---------------------------------------------------------------------------
__device__ float g_h   [(size_t)NTOK * DIM];    // 32 MB   h = x@Wm + bm  (== t rows)
__device__ float g_comb[(size_t)NTOK * DIM];    // 32 MB   combined expert outputs
__device__ float g_hmid[(size_t)NPAIR * II];    // 256 MB  gelu(t@W1+b1) permuted
__device__ float g_eo  [(size_t)NPAIR * HD];    // 64 MB   expert outputs permuted
__device__ int   g_topi[NPAIR];
__device__ float g_topw[NPAIR];
__device__ int   g_perm[NPAIR];                 // slot -> sub-token index
__device__ int   g_pos [NPAIR];                 // (t,k) -> slot
__device__ int   g_counts[NE];
__device__ int   g_cursor[NE];
__device__ int   g_offsets[NE + 1];

__device__ __forceinline__ float gelu_exact(float x) {
    return 0.5f * x * (1.0f + erff(x * 0.70710678118654752440f));
}

// ---------------------------------------------------------------------------
// Generic SGEMM + bias:  C[M,N] = A[M,K] @ B[K,N] + bias[N]
// BM=BN=128, BK=16, 256 threads, 8x8 microtile. M,N,K multiples of tile dims.
// ---------------------------------------------------------------------------
#define TBM 128
#define TBN 128
#define TBK 16
#define TTM 8
#define TTN 8

__global__ __launch_bounds__(256, 2)
void sgemm_bias(const float* __restrict__ A, const float* __restrict__ B,
                const float* __restrict__ bias, float* __restrict__ C,
                int M, int N, int K)
{
    __shared__ __align__(16) float As[TBK][TBM];
    __shared__ __align__(16) float Bs[TBK][TBN];

    const int tid = threadIdx.x;
    const int tx  = tid & 15;
    const int ty  = tid >> 4;
    const int m0  = blockIdx.y * TBM;
    const int n0  = blockIdx.x * TBN;

    float acc[TTM][TTN];
#pragma unroll
    for (int i = 0; i < TTM; i++)
#pragma unroll
        for (int j = 0; j < TTN; j++) acc[i][j] = 0.0f;

    for (int k0 = 0; k0 < K; k0 += TBK) {
#pragma unroll
        for (int v = 0; v < 2; v++) {
            int f = tid + v * 256;
            // A tile: 128 rows x 16 cols = 512 float4
            int r = f >> 2;
            int c = (f & 3) << 2;
            float4 av = *reinterpret_cast<const float4*>(A + (size_t)(m0 + r) * K + k0 + c);
            As[c + 0][r] = av.x; As[c + 1][r] = av.y;
            As[c + 2][r] = av.z; As[c + 3][r] = av.w;
            // B tile: 16 rows x 128 cols = 512 float4
            int rb = f >> 5;
            int cb = (f & 31) << 2;
            *reinterpret_cast<float4*>(&Bs[rb][cb]) =
                *reinterpret_cast<const float4*>(B + (size_t)(k0 + rb) * N + n0 + cb);
        }
        __syncthreads();
#pragma unroll
        for (int kk = 0; kk < TBK; kk++) {
            float a[TTM], b[TTN];
            *reinterpret_cast<float4*>(&a[0]) = *reinterpret_cast<const float4*>(&As[kk][ty * TTM]);
            *reinterpret_cast<float4*>(&a[4]) = *reinterpret_cast<const float4*>(&As[kk][ty * TTM + 4]);
            *reinterpret_cast<float4*>(&b[0]) = *reinterpret_cast<const float4*>(&Bs[kk][tx * TTN]);
            *reinterpret_cast<float4*>(&b[4]) = *reinterpret_cast<const float4*>(&Bs[kk][tx * TTN + 4]);
#pragma unroll
            for (int i = 0; i < TTM; i++)
#pragma unroll
                for (int j = 0; j < TTN; j++) acc[i][j] = fmaf(a[i], b[j], acc[i][j]);
        }
        __syncthreads();
    }

    const int n = n0 + tx * TTN;
    float bv[TTN];
#pragma unroll
    for (int j = 0; j < TTN; j++) bv[j] = bias[n + j];

#pragma unroll
    for (int i = 0; i < TTM; i++) {
        float4 o0, o1;
        o0.x = acc[i][0] + bv[0]; o0.y = acc[i][1] + bv[1];
        o0.z = acc[i][2] + bv[2]; o0.w = acc[i][3] + bv[3];
        o1.x = acc[i][4] + bv[4]; o1.y = acc[i][5] + bv[5];
        o1.z = acc[i][6] + bv[6]; o1.w = acc[i][7] + bv[7];
        float* crow = C + (size_t)(m0 + ty * TTM + i) * N + n;
        *reinterpret_cast<float4*>(crow)     = o0;
        *reinterpret_cast<float4*>(crow + 4) = o1;
    }
}

// ---------------------------------------------------------------------------
// Grouped (per-expert) GEMM with optional row gather and optional exact GELU.
//   rows = g_counts[e]; output row index == global slot (segBase + local row)
//   gatherA: A row source = g_perm[slot]*K (gather sub-token rows of g_h)
//   else:    A row source = slot*K        (dense permuted hmid)
// grid = (mTiles, NE, N/128)
// ---------------------------------------------------------------------------
__global__ __launch_bounds__(256, 2)
void grouped_gemm(const float* __restrict__ Asrc, const float* __restrict__ Ball,
                  const float* __restrict__ biasAll, float* __restrict__ Cout,
                  int K, int N, int doGelu, int gatherA)
{
    const int e    = blockIdx.y;
    const int rows = g_counts[e];
    const int m0   = blockIdx.x * TBM;
    if (m0 >= rows) return;
    const int segBase = g_offsets[e];
    const int n0      = blockIdx.z * TBN;
    const float* B    = Ball    + (size_t)e * K * N;
    const float* bias = biasAll + (size_t)e * N;

    __shared__ __align__(16) float As[TBK][TBM];
    __shared__ __align__(16) float Bs[TBK][TBN];

    const int tid = threadIdx.x;
    const int tx  = tid & 15;
    const int ty  = tid >> 4;

    // Precompute A source offsets for this thread's two load rows
    int    lrow[2];
    size_t aoff[2];
    bool   lval[2];
#pragma unroll
    for (int v = 0; v < 2; v++) {
        int f = tid + v * 256;
        int r = f >> 2;
        lrow[v] = r;
        int gr = m0 + r;
        lval[v] = (gr < rows);
        if (lval[v]) {
            int slot = segBase + gr;
            aoff[v] = gatherA ? (size_t)g_perm[slot] * K : (size_t)slot * K;
        } else {
            aoff[v] = 0;
        }
    }

    float acc[TTM][TTN];
#pragma unroll
    for (int i = 0; i < TTM; i++)
#pragma unroll
        for (int j = 0; j < TTN; j++) acc[i][j] = 0.0f;

    for (int k0 = 0; k0 < K; k0 += TBK) {
#pragma unroll
        for (int v = 0; v < 2; v++) {
            int f = tid + v * 256;
            int r = lrow[v];
            int c = (f & 3) << 2;
            float4 av = make_float4(0.f, 0.f, 0.f, 0.f);
            if (lval[v])
                av = *reinterpret_cast<const float4*>(Asrc + aoff[v] + k0 + c);
            As[c + 0][r] = av.x; As[c + 1][r] = av.y;
            As[c + 2][r] = av.z; As[c + 3][r] = av.w;
            int rb = f >> 5;
            int cb = (f & 31) << 2;
            *reinterpret_cast<float4*>(&Bs[rb][cb]) =
                *reinterpret_cast<const float4*>(B + (size_t)(k0 + rb) * N + n0 + cb);
        }
        __syncthreads();
#pragma unroll
        for (int kk = 0; kk < TBK; kk++) {
            float a[TTM], b[TTN];
            *reinterpret_cast<float4*>(&a[0]) = *reinterpret_cast<const float4*>(&As[kk][ty * TTM]);
            *reinterpret_cast<float4*>(&a[4]) = *reinterpret_cast<const float4*>(&As[kk][ty * TTM + 4]);
            *reinterpret_cast<float4*>(&b[0]) = *reinterpret_cast<const float4*>(&Bs[kk][tx * TTN]);
            *reinterpret_cast<float4*>(&b[4]) = *reinterpret_cast<const float4*>(&Bs[kk][tx * TTN + 4]);
#pragma unroll
            for (int i = 0; i < TTM; i++)
#pragma unroll
                for (int j = 0; j < TTN; j++) acc[i][j] = fmaf(a[i], b[j], acc[i][j]);
        }
        __syncthreads();
    }

    const int n = n0 + tx * TTN;
    float bv[TTN];
#pragma unroll
    for (int j = 0; j < TTN; j++) bv[j] = bias[n + j];

#pragma unroll
    for (int i = 0; i < TTM; i++) {
        int gr = m0 + ty * TTM + i;
        if (gr >= rows) continue;
        float o[TTN];
#pragma unroll
        for (int j = 0; j < TTN; j++) {
            float vv = acc[i][j] + bv[j];
            o[j] = doGelu ? gelu_exact(vv) : vv;
        }
        float* crow = Cout + (size_t)(segBase + gr) * N + n;
        *reinterpret_cast<float4*>(crow)     = make_float4(o[0], o[1], o[2], o[3]);
        *reinterpret_cast<float4*>(crow + 4) = make_float4(o[4], o[5], o[6], o[7]);
    }
}

// ---------------------------------------------------------------------------
// Routing: one warp per sub-token. logits = t @ emb[HD,NE]; softmax; top-2.
// ---------------------------------------------------------------------------
__global__ void routing_kernel(const float* __restrict__ emb)
{
    const int warp = (blockIdx.x * blockDim.x + threadIdx.x) >> 5;
    const int lane = threadIdx.x & 31;
    if (warp >= NSUB) return;

    const float* trow = g_h + (size_t)warp * HD;
    const float tv0 = trow[lane];
    const float tv1 = trow[lane + 32];
    const float tv2 = trow[lane + 64];
    const float tv3 = trow[lane + 96];

    float logits[NE];
#pragma unroll
    for (int e = 0; e < NE; e++) {
        float p = tv0 * emb[(lane      ) * NE + e]
                + tv1 * emb[(lane + 32 ) * NE + e]
                + tv2 * emb[(lane + 64 ) * NE + e]
                + tv3 * emb[(lane + 96 ) * NE + e];
#pragma unroll
        for (int s = 16; s > 0; s >>= 1) p += __shfl_xor_sync(0xffffffffu, p, s);
        logits[e] = p;
    }

    float mx = logits[0];
#pragma unroll
    for (int e = 1; e < NE; e++) mx = fmaxf(mx, logits[e]);
    float sum = 0.0f;
#pragma unroll
    for (int e = 0; e < NE; e++) { logits[e] = expf(logits[e] - mx); sum += logits[e]; }
    const float inv = 1.0f / sum;

    // top-2 (first index wins ties, matching jax top_k)
    int i0 = 0; float v0 = logits[0];
#pragma unroll
    for (int e = 1; e < NE; e++) if (logits[e] > v0) { v0 = logits[e]; i0 = e; }
    int i1 = -1; float v1 = -1.0f;
#pragma unroll
    for (int e = 0; e < NE; e++) if (e != i0 && logits[e] > v1) { v1 = logits[e]; i1 = e; }

    if (lane == 0) {
        g_topi[2 * warp + 0] = i0;
        g_topi[2 * warp + 1] = i1;
        g_topw[2 * warp + 0] = v0 * inv;
        g_topw[2 * warp + 1] = v1 * inv;
    }
}

// ---------------------------------------------------------------------------
// Routing bookkeeping
// ---------------------------------------------------------------------------
__global__ void zero_counts() {
    int i = threadIdx.x;
    if (i < NE) { g_counts[i] = 0; g_cursor[i] = 0; }
}
__global__ void hist_kernel() {
    int i = blockIdx.x * blockDim.x + threadIdx.x;
    if (i < NPAIR) atomicAdd(&g_counts[g_topi[i]], 1);
}
__global__ void scan_kernel() {
    int s = 0;
    for (int e = 0; e < NE; e++) { g_offsets[e] = s; s += g_counts[e]; }
    g_offsets[NE] = s;
}
__global__ void scatter_kernel() {
    int i = blockIdx.x * blockDim.x + threadIdx.x;
    if (i < NPAIR) {
        int e = g_topi[i];
        int slot = g_offsets[e] + atomicAdd(&g_cursor[e], 1);
        g_perm[slot] = i >> 1;   // sub-token index
        g_pos[i] = slot;
    }
}

// ---------------------------------------------------------------------------
// Combine: comb[t, :] = w0 * eo[pos0, :] + w1 * eo[pos1, :]
// ---------------------------------------------------------------------------
__global__ void combine_kernel() {
    int idx = blockIdx.x * blockDim.x + threadIdx.x;   // over NSUB*HD
    int t = idx >> 7;
    int j = idx & 127;
    float w0 = g_topw[2 * t + 0];
    float w1 = g_topw[2 * t + 1];
    int   s0 = g_pos [2 * t + 0];
    int   s1 = g_pos [2 * t + 1];
    g_comb[idx] = w0 * g_eo[(size_t)s0 * HD + j] + w1 * g_eo[(size_t)s1 * HD + j];
}

// ---------------------------------------------------------------------------
// Launch
// ---------------------------------------------------------------------------
extern "C" void kernel_launch(void* const* d_in, const int* in_sizes, int n_in,
                              void* d_out, int out_size)
{
    (void)in_sizes; (void)n_in; (void)out_size;
    const float* x   = (const float*)d_in[0];
    const float* Wm  = (const float*)d_in[1];
    const float* bm  = (const float*)d_in[2];
    const float* emb = (const float*)d_in[3];
    const float* W1  = (const float*)d_in[4];
    const float* b1  = (const float*)d_in[5];
    const float* W2  = (const float*)d_in[6];
    const float* b2  = (const float*)d_in[7];
    const float* Wo  = (const float*)d_in[8];
    const float* bo  = (const float*)d_in[9];
    float* out = (float*)d_out;

    float *h_p, *comb_p, *hmid_p, *eo_p;
    cudaGetSymbolAddress((void**)&h_p,    g_h);
    cudaGetSymbolAddress((void**)&comb_p, g_comb);
    cudaGetSymbolAddress((void**)&hmid_p, g_hmid);
    cudaGetSymbolAddress((void**)&eo_p,   g_eo);

    // 1) h = x @ Wm + bm   [8192,1024]x[1024,1024]
    sgemm_bias<<<dim3(DIM / TBN, NTOK / TBM), 256>>>(x, Wm, bm, h_p, NTOK, DIM, DIM);

    // 2) routing (warp per sub-token)
    routing_kernel<<<NSUB / 8, 256>>>(emb);

    // 3) expert assignment bookkeeping
    zero_counts<<<1, 32>>>();
    hist_kernel<<<NPAIR / 256, 256>>>();
    scan_kernel<<<1, 1>>>();
    scatter_kernel<<<NPAIR / 256, 256>>>();

    // 4) grouped GEMM1 + GELU: hmid = gelu(t @ W1[e] + b1[e])   K=128, N=512
    grouped_gemm<<<dim3(NPAIR / TBM, NE, II / TBN), 256>>>(h_p, W1, b1, hmid_p, HD, II, 1, 1);

    // 5) grouped GEMM2: eo = hmid @ W2[e] + b2[e]   K=512, N=128
    grouped_gemm<<<dim3(NPAIR / TBM, NE, HD / TBN), 256>>>(hmid_p, W2, b2, eo_p, II, HD, 0, 0);

    // 6) combine top-2 expert outputs with router weights
    combine_kernel<<<(NSUB * HD) / 256, 256>>>();

    // 7) out = comb @ Wo + bo   [8192,1024]x[1024,1024]
    sgemm_bias<<<dim3(DIM / TBN, NTOK / TBM), 256>>>(comb_p, Wo, bo, out, NTOK, DIM, DIM);
}

// round 3
// speedup vs baseline: 1.6653x; 1.6653x over previous
#include <cuda_runtime.h>
#include <cuda_bf16.h>
#include <math.h>
#include <stdint.h>

// ---------------------------------------------------------------------------
// Problem constants
// ---------------------------------------------------------------------------
#define BSZ   4
#define LEN   2048
#define DIM   1024
#define NH    8
#define NE    16
#define TOPK  2
#define HD    128
#define II    512
#define NTOK  (BSZ*LEN)    // 8192
#define NSUB  (NTOK*NH)    // 65536
#define NPAIR (NSUB*TOPK)  // 131072

// ---------------------------------------------------------------------------
// Device scratch
// ---------------------------------------------------------------------------
__device__ float g_h   [(size_t)NTOK * DIM];
__device__ float g_comb[(size_t)NTOK * DIM];
__device__ float g_hmid[(size_t)NPAIR * II];
__device__ float g_eo  [(size_t)NPAIR * HD];
__device__ int   g_topi[NPAIR];
__device__ float g_topw[NPAIR];
__device__ int   g_perm[NPAIR];
__device__ int   g_pos [NPAIR];
__device__ int   g_counts[NE];
__device__ int   g_cursor[NE];
__device__ int   g_offsets[NE + 1];

// Prepacked weights: hi/lo bf16x2 (packed along k), transposed to [N][K/2]
__device__ uint32_t g_WmH[(size_t)DIM * DIM / 2];
__device__ uint32_t g_WmL[(size_t)DIM * DIM / 2];
__device__ uint32_t g_W1H[(size_t)NE * II * HD / 2];
__device__ uint32_t g_W1L[(size_t)NE * II * HD / 2];
__device__ uint32_t g_W2H[(size_t)NE * HD * II / 2];
__device__ uint32_t g_W2L[(size_t)NE * HD * II / 2];
__device__ uint32_t g_WoH[(size_t)DIM * DIM / 2];
__device__ uint32_t g_WoL[(size_t)DIM * DIM / 2];

__device__ __forceinline__ float gelu_exact(float x) {
    return 0.5f * x * (1.0f + erff(x * 0.70710678118654752440f));
}

// pack two floats into bf16x2: low 16 bits = e0 (even k), high = e1 (odd k)
__device__ __forceinline__ uint32_t pack_bf16x2(float e0, float e1) {
    uint32_t r;
    asm("cvt.rn.bf16x2.f32 %0, %1, %2;" : "=r"(r) : "f"(e1), "f"(e0));
    return r;
}
__device__ __forceinline__ float bf16_rt(float x) {   // round-trip through bf16
    return __bfloat162float(__float2bfloat16(x));
}

__device__ __forceinline__ void mma_bf16(float* d, const uint32_t* a, const uint32_t* b) {
    asm volatile(
        "mma.sync.aligned.m16n8k16.row.col.f32.bf16.bf16.f32 "
        "{%0,%1,%2,%3}, {%4,%5,%6,%7}, {%8,%9}, {%0,%1,%2,%3};\n"
        : "+f"(d[0]), "+f"(d[1]), "+f"(d[2]), "+f"(d[3])
        : "r"(a[0]), "r"(a[1]), "r"(a[2]), "r"(a[3]), "r"(b[0]), "r"(b[1]));
}

// ---------------------------------------------------------------------------
// Weight prepack: B[K][N] (row-major, per expert) -> hi/lo [N][K/2] uint32
// (bf16 pair packed along k). Tiled smem transpose: 64 k-rows x 32 n-cols.
// grid = (N/32, K/64, E), block = 256.
// ---------------------------------------------------------------------------
__global__ void prepack_kernel(const float* __restrict__ B,
                               uint32_t* __restrict__ Hi, uint32_t* __restrict__ Lo,
                               int K, int N)
{
    const int e = blockIdx.z;
    B  += (size_t)e * K * N;
    Hi += (size_t)e * N * (K / 2);
    Lo += (size_t)e * N * (K / 2);

    __shared__ float tile[64][33];
    const int tid = threadIdx.x;
    const int k0 = blockIdx.y * 64;
    const int n0 = blockIdx.x * 32;

#pragma unroll
    for (int i = 0; i < 8; i++) {
        const int row = i * 8 + (tid >> 5);
        const int col = tid & 31;
        tile[row][col] = B[(size_t)(k0 + row) * N + n0 + col];
    }
    __syncthreads();

#pragma unroll
    for (int j = 0; j < 4; j++) {
        const int nl = (tid >> 5) * 4 + j;
        const int kp = tid & 31;
        const float x0 = tile[2 * kp][nl];
        const float x1 = tile[2 * kp + 1][nl];
        const float h0 = bf16_rt(x0), h1 = bf16_rt(x1);
        const size_t o = (size_t)(n0 + nl) * (K / 2) + k0 / 2 + kp;
        Hi[o] = pack_bf16x2(h0, h1);
        Lo[o] = pack_bf16x2(x0 - h0, x1 - h1);
    }
}

// ---------------------------------------------------------------------------
// bf16-split tensor GEMM: C[M,N] = op(A[M,K] @ B[K,N] + bias[N])
// A: fp32 row-major (split to bf16 hi/lo at staging).
// B: prepacked hi/lo [N][K/2].
// Block 128x128, K-tile 32, 256 threads (8 warps, 64x32 warp tile).
// Smem tiles [128][20] uint32 (16 kpairs + pad 4) — fragment LDS conflict-free.
// ---------------------------------------------------------------------------
template<bool GROUPED, bool GATHER, bool DO_GELU>
__global__ __launch_bounds__(256, 2)
void mma_gemm(const float* __restrict__ Asrc,
              const uint32_t* __restrict__ BpH, const uint32_t* __restrict__ BpL,
              const float* __restrict__ biasAll, float* __restrict__ Cout,
              int M, int N, int K)
{
    int rows = M, segBase = 0, m0, n0;
    const float* bias;
    if (GROUPED) {
        const int e = blockIdx.y;
        rows    = g_counts[e];
        m0      = blockIdx.x * 128;
        if (m0 >= rows) return;
        segBase = g_offsets[e];
        n0      = blockIdx.z * 128;
        BpH    += (size_t)e * N * (K / 2);
        BpL    += (size_t)e * N * (K / 2);
        bias    = biasAll + (size_t)e * N;
    } else {
        m0   = blockIdx.y * 128;
        n0   = blockIdx.x * 128;
        bias = biasAll;
    }

    __shared__ uint32_t AsH[128][20];
    __shared__ uint32_t AsL[128][20];
    __shared__ uint32_t BsH[128][20];
    __shared__ uint32_t BsL[128][20];

    const int tid  = threadIdx.x;
    const int lane = tid & 31;
    const int wid  = tid >> 5;
    const int g    = lane >> 2;     // 0..7
    const int tig  = lane & 3;      // 0..3
    const int wm   = (wid & 1) * 64;
    const int wn   = (wid >> 1) * 32;

    // A loads: thread covers 4 rows, float4 at col (tid&7)*4
    const int acol = (tid & 7) * 4;
    const float* arow[4];
    bool aval[4];
#pragma unroll
    for (int v = 0; v < 4; v++) {
        const int r  = v * 32 + (tid >> 3);
        const int gr = m0 + r;
        if (GROUPED) {
            aval[v] = (gr < rows);
            int row = 0;
            if (aval[v]) row = GATHER ? g_perm[segBase + gr] : (segBase + gr);
            arow[v] = Asrc + (size_t)row * K + acol;
        } else {
            aval[v] = true;
            arow[v] = Asrc + (size_t)gr * K + acol;
        }
    }

    // B loads: thread covers col = tid>>1, 8 kpairs starting (tid&1)*8
    const int bcol  = tid >> 1;
    const int bkp   = (tid & 1) * 8;
    const uint32_t* bptrH = BpH + (size_t)(n0 + bcol) * (K / 2) + bkp;
    const uint32_t* bptrL = BpL + (size_t)(n0 + bcol) * (K / 2) + bkp;

    float acc[4][4][4];
#pragma unroll
    for (int m = 0; m < 4; m++)
#pragma unroll
        for (int n = 0; n < 4; n++)
#pragma unroll
            for (int i = 0; i < 4; i++) acc[m][n][i] = 0.0f;

    for (int k0 = 0; k0 < K; k0 += 32) {
        // --- stage A (128x32 fp32 -> hi/lo bf16x2) ---
#pragma unroll
        for (int v = 0; v < 4; v++) {
            float4 av = make_float4(0.f, 0.f, 0.f, 0.f);
            if (aval[v]) av = *reinterpret_cast<const float4*>(arow[v] + k0);
            const int r = v * 32 + (tid >> 3);
            const float hx = bf16_rt(av.x), hy = bf16_rt(av.y);
            const float hz = bf16_rt(av.z), hw = bf16_rt(av.w);
            uint2 hv, lv;
            hv.x = pack_bf16x2(hx, hy);
            hv.y = pack_bf16x2(hz, hw);
            lv.x = pack_bf16x2(av.x - hx, av.y - hy);
            lv.y = pack_bf16x2(av.z - hz, av.w - hw);
            *reinterpret_cast<uint2*>(&AsH[r][acol >> 1]) = hv;
            *reinterpret_cast<uint2*>(&AsL[r][acol >> 1]) = lv;
        }
        // --- stage B (prepacked, straight copy) ---
        {
            const int kpo = k0 >> 1;
            uint4 h0 = *reinterpret_cast<const uint4*>(bptrH + kpo);
            uint4 h1 = *reinterpret_cast<const uint4*>(bptrH + kpo + 4);
            uint4 l0 = *reinterpret_cast<const uint4*>(bptrL + kpo);
            uint4 l1 = *reinterpret_cast<const uint4*>(bptrL + kpo + 4);
            *reinterpret_cast<uint4*>(&BsH[bcol][bkp])     = h0;
            *reinterpret_cast<uint4*>(&BsH[bcol][bkp + 4]) = h1;
            *reinterpret_cast<uint4*>(&BsL[bcol][bkp])     = l0;
            *reinterpret_cast<uint4*>(&BsL[bcol][bkp + 4]) = l1;
        }
        __syncthreads();

#pragma unroll
        for (int ks = 0; ks < 2; ks++) {
            const int kk = ks * 8;
            uint32_t bH[4][2], bL[4][2];
#pragma unroll
            for (int n = 0; n < 4; n++) {
                const int nc = wn + n * 8 + g;
                bH[n][0] = BsH[nc][kk + tig];
                bH[n][1] = BsH[nc][kk + tig + 4];
                bL[n][0] = BsL[nc][kk + tig];
                bL[n][1] = BsL[nc][kk + tig + 4];
            }
#pragma unroll
            for (int m = 0; m < 4; m++) {
                const int mr = wm + m * 16 + g;
                uint32_t aH[4], aL[4];
                aH[0] = AsH[mr    ][kk + tig];
                aH[1] = AsH[mr + 8][kk + tig];
                aH[2] = AsH[mr    ][kk + tig + 4];
                aH[3] = AsH[mr + 8][kk + tig + 4];
                aL[0] = AsL[mr    ][kk + tig];
                aL[1] = AsL[mr + 8][kk + tig];
                aL[2] = AsL[mr    ][kk + tig + 4];
                aL[3] = AsL[mr + 8][kk + tig + 4];
#pragma unroll
                for (int n = 0; n < 4; n++) {
                    mma_bf16(acc[m][n], aH, bH[n]);
                    mma_bf16(acc[m][n], aH, bL[n]);
                    mma_bf16(acc[m][n], aL, bH[n]);
                }
            }
        }
        __syncthreads();
    }

    // --- epilogue ---
#pragma unroll
    for (int n = 0; n < 4; n++) {
        const int col = n0 + wn + n * 8 + 2 * tig;
        const float b0 = bias[col];
        const float b1 = bias[col + 1];
#pragma unroll
        for (int m = 0; m < 4; m++) {
            const int r0 = wm + m * 16 + g;
            float v00 = acc[m][n][0] + b0;
            float v01 = acc[m][n][1] + b1;
            float v10 = acc[m][n][2] + b0;
            float v11 = acc[m][n][3] + b1;
            if (DO_GELU) {
                v00 = gelu_exact(v00); v01 = gelu_exact(v01);
                v10 = gelu_exact(v10); v11 = gelu_exact(v11);
            }
            if (GROUPED) {
                if (m0 + r0 < rows) {
                    float* p = Cout + (size_t)(segBase + m0 + r0) * N + col;
                    *reinterpret_cast<float2*>(p) = make_float2(v00, v01);
                }
                if (m0 + r0 + 8 < rows) {
                    float* p = Cout + (size_t)(segBase + m0 + r0 + 8) * N + col;
                    *reinterpret_cast<float2*>(p) = make_float2(v10, v11);
                }
            } else {
                float* p0 = Cout + (size_t)(m0 + r0) * N + col;
                float* p1 = Cout + (size_t)(m0 + r0 + 8) * N + col;
                *reinterpret_cast<float2*>(p0) = make_float2(v00, v01);
                *reinterpret_cast<float2*>(p1) = make_float2(v10, v11);
            }
        }
    }
}

// ---------------------------------------------------------------------------
// Routing: one warp per sub-token.
// ---------------------------------------------------------------------------
__global__ void routing_kernel(const float* __restrict__ emb)
{
    const int warp = (blockIdx.x * blockDim.x + threadIdx.x) >> 5;
    const int lane = threadIdx.x & 31;
    if (warp >= NSUB) return;

    const float* trow = g_h + (size_t)warp * HD;
    const float tv0 = trow[lane];
    const float tv1 = trow[lane + 32];
    const float tv2 = trow[lane + 64];
    const float tv3 = trow[lane + 96];

    float logits[NE];
#pragma unroll
    for (int e = 0; e < NE; e++) {
        float p = tv0 * emb[(lane      ) * NE + e]
                + tv1 * emb[(lane + 32 ) * NE + e]
                + tv2 * emb[(lane + 64 ) * NE + e]
                + tv3 * emb[(lane + 96 ) * NE + e];
#pragma unroll
        for (int s = 16; s > 0; s >>= 1) p += __shfl_xor_sync(0xffffffffu, p, s);
        logits[e] = p;
    }

    float mx = logits[0];
#pragma unroll
    for (int e = 1; e < NE; e++) mx = fmaxf(mx, logits[e]);
    float sum = 0.0f;
#pragma unroll
    for (int e = 0; e < NE; e++) { logits[e] = expf(logits[e] - mx); sum += logits[e]; }
    const float inv = 1.0f / sum;

    int i0 = 0; float v0 = logits[0];
#pragma unroll
    for (int e = 1; e < NE; e++) if (logits[e] > v0) { v0 = logits[e]; i0 = e; }
    int i1 = -1; float v1 = -1.0f;
#pragma unroll
    for (int e = 0; e < NE; e++) if (e != i0 && logits[e] > v1) { v1 = logits[e]; i1 = e; }

    if (lane == 0) {
        g_topi[2 * warp + 0] = i0;
        g_topi[2 * warp + 1] = i1;
        g_topw[2 * warp + 0] = v0 * inv;
        g_topw[2 * warp + 1] = v1 * inv;
    }
}

// ---------------------------------------------------------------------------
// Routing bookkeeping
// ---------------------------------------------------------------------------
__global__ void zero_counts() {
    int i = threadIdx.x;
    if (i < NE) { g_counts[i] = 0; g_cursor[i] = 0; }
}
__global__ void hist_kernel() {
    int i = blockIdx.x * blockDim.x + threadIdx.x;
    if (i < NPAIR) atomicAdd(&g_counts[g_topi[i]], 1);
}
__global__ void scan_kernel() {
    int s = 0;
    for (int e = 0; e < NE; e++) { g_offsets[e] = s; s += g_counts[e]; }
    g_offsets[NE] = s;
}
__global__ void scatter_kernel() {
    int i = blockIdx.x * blockDim.x + threadIdx.x;
    if (i < NPAIR) {
        int e = g_topi[i];
        int slot = g_offsets[e] + atomicAdd(&g_cursor[e], 1);
        g_perm[slot] = i >> 1;
        g_pos[i] = slot;
    }
}

// ---------------------------------------------------------------------------
// Combine
// ---------------------------------------------------------------------------
__global__ void combine_kernel() {
    int idx = blockIdx.x * blockDim.x + threadIdx.x;
    int t = idx >> 7;
    int j = idx & 127;
    float w0 = g_topw[2 * t + 0];
    float w1 = g_topw[2 * t + 1];
    int   s0 = g_pos [2 * t + 0];
    int   s1 = g_pos [2 * t + 1];
    g_comb[idx] = w0 * g_eo[(size_t)s0 * HD + j] + w1 * g_eo[(size_t)s1 * HD + j];
}

// ---------------------------------------------------------------------------
// Launch
// ---------------------------------------------------------------------------
extern "C" void kernel_launch(void* const* d_in, const int* in_sizes, int n_in,
                              void* d_out, int out_size)
{
    (void)in_sizes; (void)n_in; (void)out_size;
    const float* x   = (const float*)d_in[0];
    const float* Wm  = (const float*)d_in[1];
    const float* bm  = (const float*)d_in[2];
    const float* emb = (const float*)d_in[3];
    const float* W1  = (const float*)d_in[4];
    const float* b1  = (const float*)d_in[5];
    const float* W2  = (const float*)d_in[6];
    const float* b2  = (const float*)d_in[7];
    const float* Wo  = (const float*)d_in[8];
    const float* bo  = (const float*)d_in[9];
    float* out = (float*)d_out;

    float *h_p, *comb_p, *hmid_p, *eo_p;
    cudaGetSymbolAddress((void**)&h_p,    g_h);
    cudaGetSymbolAddress((void**)&comb_p, g_comb);
    cudaGetSymbolAddress((void**)&hmid_p, g_hmid);
    cudaGetSymbolAddress((void**)&eo_p,   g_eo);
    uint32_t *WmH, *WmL, *W1H, *W1L, *W2H, *W2L, *WoH, *WoL;
    cudaGetSymbolAddress((void**)&WmH, g_WmH); cudaGetSymbolAddress((void**)&WmL, g_WmL);
    cudaGetSymbolAddress((void**)&W1H, g_W1H); cudaGetSymbolAddress((void**)&W1L, g_W1L);
    cudaGetSymbolAddress((void**)&W2H, g_W2H); cudaGetSymbolAddress((void**)&W2L, g_W2L);
    cudaGetSymbolAddress((void**)&WoH, g_WoH); cudaGetSymbolAddress((void**)&WoL, g_WoL);

    // 0) prepack weights (transpose + bf16 hi/lo split)
    prepack_kernel<<<dim3(DIM/32, DIM/64, 1),  256>>>(Wm, WmH, WmL, DIM, DIM);
    prepack_kernel<<<dim3(II/32,  HD/64,  NE), 256>>>(W1, W1H, W1L, HD, II);
    prepack_kernel<<<dim3(HD/32,  II/64,  NE), 256>>>(W2, W2H, W2L, II, HD);
    prepack_kernel<<<dim3(DIM/32, DIM/64, 1),  256>>>(Wo, WoH, WoL, DIM, DIM);

    // 1) h = x @ Wm + bm
    mma_gemm<false,false,false><<<dim3(DIM/128, NTOK/128), 256>>>(
        x, WmH, WmL, bm, h_p, NTOK, DIM, DIM);

    // 2) routing
    routing_kernel<<<NSUB / 8, 256>>>(emb);

    // 3) expert bookkeeping
    zero_counts<<<1, 32>>>();
    hist_kernel<<<NPAIR / 256, 256>>>();
    scan_kernel<<<1, 1>>>();
    scatter_kernel<<<NPAIR / 256, 256>>>();

    // 4) hmid = gelu(t @ W1[e] + b1[e])   K=128, N=512 (gathered A)
    mma_gemm<true,true,true><<<dim3(NPAIR/128, NE, II/128), 256>>>(
        h_p, W1H, W1L, b1, hmid_p, 0, II, HD);

    // 5) eo = hmid @ W2[e] + b2[e]        K=512, N=128
    mma_gemm<true,false,false><<<dim3(NPAIR/128, NE, HD/128), 256>>>(
        hmid_p, W2H, W2L, b2, eo_p, 0, HD, II);

    // 6) combine
    combine_kernel<<<(NSUB * HD) / 256, 256>>>();

    // 7) out = comb @ Wo + bo
    mma_gemm<false,false,false><<<dim3(DIM/128, NTOK/128), 256>>>(
        comb_p, WoH, WoL, bo, out, NTOK, DIM, DIM);
}

// round 4
// speedup vs baseline: 1.8831x; 1.1308x over previous
#include <cuda_runtime.h>
#include <cuda_bf16.h>
#include <math.h>
#include <stdint.h>

// ---------------------------------------------------------------------------
// Problem constants
// ---------------------------------------------------------------------------
#define BSZ   4
#define LEN   2048
#define DIM   1024
#define NH    8
#define NE    16
#define TOPK  2
#define HD    128
#define II    512
#define NTOK  (BSZ*LEN)    // 8192
#define NSUB  (NTOK*NH)    // 65536
#define NPAIR (NSUB*TOPK)  // 131072

// ---------------------------------------------------------------------------
// Device scratch
// ---------------------------------------------------------------------------
__device__ float g_h   [(size_t)NTOK * DIM];
__device__ float g_comb[(size_t)NTOK * DIM];
__device__ float g_hmid[(size_t)NPAIR * II];
__device__ float g_eo  [(size_t)NPAIR * HD];
__device__ int   g_topi[NPAIR];
__device__ float g_topw[NPAIR];
__device__ int   g_perm[NPAIR];
__device__ int   g_pos [NPAIR];
__device__ int   g_counts[NE];
__device__ int   g_cursor[NE];
__device__ int   g_offsets[NE + 1];

// Prepacked weights: hi/lo bf16x2 (packed along k), transposed to [N][K/2]
__device__ uint32_t g_WmH[(size_t)DIM * DIM / 2];
__device__ uint32_t g_WmL[(size_t)DIM * DIM / 2];
__device__ uint32_t g_W1H[(size_t)NE * II * HD / 2];
__device__ uint32_t g_W1L[(size_t)NE * II * HD / 2];
__device__ uint32_t g_W2H[(size_t)NE * HD * II / 2];
__device__ uint32_t g_W2L[(size_t)NE * HD * II / 2];
__device__ uint32_t g_WoH[(size_t)DIM * DIM / 2];
__device__ uint32_t g_WoL[(size_t)DIM * DIM / 2];

__device__ __forceinline__ float gelu_exact(float x) {
    return 0.5f * x * (1.0f + erff(x * 0.70710678118654752440f));
}

__device__ __forceinline__ uint32_t pack_bf16x2(float e0, float e1) {
    uint32_t r;
    asm("cvt.rn.bf16x2.f32 %0, %1, %2;" : "=r"(r) : "f"(e1), "f"(e0));
    return r;
}
__device__ __forceinline__ float bf16_rt(float x) {
    return __bfloat162float(__float2bfloat16(x));
}

__device__ __forceinline__ void mma_bf16(float* d, const uint32_t* a, const uint32_t* b) {
    asm volatile(
        "mma.sync.aligned.m16n8k16.row.col.f32.bf16.bf16.f32 "
        "{%0,%1,%2,%3}, {%4,%5,%6,%7}, {%8,%9}, {%0,%1,%2,%3};\n"
        : "+f"(d[0]), "+f"(d[1]), "+f"(d[2]), "+f"(d[3])
        : "r"(a[0]), "r"(a[1]), "r"(a[2]), "r"(a[3]), "r"(b[0]), "r"(b[1]));
}

__device__ __forceinline__ void ldsm_x4(uint32_t& r0, uint32_t& r1,
                                        uint32_t& r2, uint32_t& r3, uint32_t addr) {
    asm volatile("ldmatrix.sync.aligned.m8n8.x4.shared.b16 {%0,%1,%2,%3}, [%4];"
                 : "=r"(r0), "=r"(r1), "=r"(r2), "=r"(r3) : "r"(addr));
}

__device__ __forceinline__ uint32_t smem_u32(const void* p) {
    return (uint32_t)__cvta_generic_to_shared(p);
}

#define CP16(dst, src) \
    asm volatile("cp.async.cg.shared.global [%0], [%1], 16;" :: "r"(dst), "l"(src))

// ---------------------------------------------------------------------------
// Weight prepack: B[K][N] (row-major, per expert) -> hi/lo [N][K/2] uint32
// ---------------------------------------------------------------------------
__global__ void prepack_kernel(const float* __restrict__ B,
                               uint32_t* __restrict__ Hi, uint32_t* __restrict__ Lo,
                               int K, int N)
{
    const int e = blockIdx.z;
    B  += (size_t)e * K * N;
    Hi += (size_t)e * N * (K / 2);
    Lo += (size_t)e * N * (K / 2);

    __shared__ float tile[64][33];
    const int tid = threadIdx.x;
    const int k0 = blockIdx.y * 64;
    const int n0 = blockIdx.x * 32;

#pragma unroll
    for (int i = 0; i < 8; i++) {
        const int row = i * 8 + (tid >> 5);
        const int col = tid & 31;
        tile[row][col] = B[(size_t)(k0 + row) * N + n0 + col];
    }
    __syncthreads();

#pragma unroll
    for (int j = 0; j < 4; j++) {
        const int nl = (tid >> 5) * 4 + j;
        const int kp = tid & 31;
        const float x0 = tile[2 * kp][nl];
        const float x1 = tile[2 * kp + 1][nl];
        const float h0 = bf16_rt(x0), h1 = bf16_rt(x1);
        const size_t o = (size_t)(n0 + nl) * (K / 2) + k0 / 2 + kp;
        Hi[o] = pack_bf16x2(h0, h1);
        Lo[o] = pack_bf16x2(x0 - h0, x1 - h1);
    }
}

// ---------------------------------------------------------------------------
// bf16-split tensor GEMM, ldmatrix fragments + cp.async B staging.
// Block 128x128, K-tile 32, 256 threads (8 warps, 64x32 warp tile).
// Smem tiles [128][20] uint32 (16 kpairs + pad 4): LDSM-conflict-free.
// ---------------------------------------------------------------------------
template<bool GROUPED, bool GATHER, bool DO_GELU>
__global__ __launch_bounds__(256, 2)
void mma_gemm(const float* __restrict__ Asrc,
              const uint32_t* __restrict__ BpH, const uint32_t* __restrict__ BpL,
              const float* __restrict__ biasAll, float* __restrict__ Cout,
              int M, int N, int K)
{
    int rows = M, segBase = 0, m0, n0;
    const float* bias;
    if (GROUPED) {
        const int e = blockIdx.y;
        rows    = g_counts[e];
        m0      = blockIdx.x * 128;
        if (m0 >= rows) return;
        segBase = g_offsets[e];
        n0      = blockIdx.z * 128;
        BpH    += (size_t)e * N * (K / 2);
        BpL    += (size_t)e * N * (K / 2);
        bias    = biasAll + (size_t)e * N;
    } else {
        m0   = blockIdx.y * 128;
        n0   = blockIdx.x * 128;
        bias = biasAll;
    }

    __shared__ __align__(16) uint32_t AsH[128][20];
    __shared__ __align__(16) uint32_t AsL[128][20];
    __shared__ __align__(16) uint32_t BsH[128][20];
    __shared__ __align__(16) uint32_t BsL[128][20];

    const int tid  = threadIdx.x;
    const int lane = tid & 31;
    const int wid  = tid >> 5;
    const int g    = lane >> 2;
    const int tig  = lane & 3;
    const int wm   = (wid & 1) * 64;
    const int wn   = (wid >> 1) * 32;

    // A loads: thread covers 4 rows, float4 at col (tid&7)*4
    const int acol = (tid & 7) * 4;
    const float* arow[4];
    bool aval[4];
#pragma unroll
    for (int v = 0; v < 4; v++) {
        const int r  = v * 32 + (tid >> 3);
        const int gr = m0 + r;
        if (GROUPED) {
            aval[v] = (gr < rows);
            int row = 0;
            if (aval[v]) row = GATHER ? g_perm[segBase + gr] : (segBase + gr);
            arow[v] = Asrc + (size_t)row * K + acol;
        } else {
            aval[v] = true;
            arow[v] = Asrc + (size_t)gr * K + acol;
        }
    }

    // B loads: thread covers col = tid>>1, 8 kpairs starting (tid&1)*8
    const int bcol  = tid >> 1;
    const int bkp   = (tid & 1) * 8;
    const uint32_t* bptrH = BpH + (size_t)(n0 + bcol) * (K / 2) + bkp;
    const uint32_t* bptrL = BpL + (size_t)(n0 + bcol) * (K / 2) + bkp;
    const uint32_t bsH_dst = smem_u32(&BsH[bcol][bkp]);
    const uint32_t bsL_dst = smem_u32(&BsL[bcol][bkp]);

    // ldmatrix per-lane source addresses (byte offsets into tiles)
    // A x4: rows (lane&15), kpair col block (lane>>4)*4
    const uint32_t a_off = (((wm + (lane & 15)) * 20) + ((lane >> 4) * 4)) * 4;
    const uint32_t aH_addr = smem_u32(&AsH[0][0]) + a_off;
    const uint32_t aL_addr = smem_u32(&AsL[0][0]) + a_off;
    // B x4: n-row = wn + ((lane>>4)&1)*8 + (lane&7), kpair block ((lane>>3)&1)*4
    const uint32_t b_off = (((wn + ((lane >> 4) & 1) * 8 + (lane & 7)) * 20)
                            + (((lane >> 3) & 1) * 4)) * 4;
    const uint32_t bH_addr = smem_u32(&BsH[0][0]) + b_off;
    const uint32_t bL_addr = smem_u32(&BsL[0][0]) + b_off;

    float acc[4][4][4];
#pragma unroll
    for (int m = 0; m < 4; m++)
#pragma unroll
        for (int n = 0; n < 4; n++)
#pragma unroll
            for (int i = 0; i < 4; i++) acc[m][n][i] = 0.0f;

    for (int k0 = 0; k0 < K; k0 += 32) {
        // --- B tile via cp.async (prepacked: straight copy), issued first ---
        {
            const int kpo = k0 >> 1;
            CP16(bsH_dst,      bptrH + kpo);
            CP16(bsH_dst + 16, bptrH + kpo + 4);
            CP16(bsL_dst,      bptrL + kpo);
            CP16(bsL_dst + 16, bptrL + kpo + 4);
            asm volatile("cp.async.commit_group;");
        }
        // --- stage A (128x32 fp32 -> hi/lo bf16x2) overlapping B loads ---
#pragma unroll
        for (int v = 0; v < 4; v++) {
            float4 av = make_float4(0.f, 0.f, 0.f, 0.f);
            if (aval[v]) av = *reinterpret_cast<const float4*>(arow[v] + k0);
            const int r = v * 32 + (tid >> 3);
            const float hx = bf16_rt(av.x), hy = bf16_rt(av.y);
            const float hz = bf16_rt(av.z), hw = bf16_rt(av.w);
            uint2 hv, lv;
            hv.x = pack_bf16x2(hx, hy);
            hv.y = pack_bf16x2(hz, hw);
            lv.x = pack_bf16x2(av.x - hx, av.y - hy);
            lv.y = pack_bf16x2(av.z - hz, av.w - hw);
            *reinterpret_cast<uint2*>(&AsH[r][acol >> 1]) = hv;
            *reinterpret_cast<uint2*>(&AsL[r][acol >> 1]) = lv;
        }
        asm volatile("cp.async.wait_group 0;" ::: "memory");
        __syncthreads();

#pragma unroll
        for (int ks = 0; ks < 2; ks++) {
            const uint32_t ksb = ks * 32;   // +8 kpairs = 32 bytes
            uint32_t bH[4][2], bL[4][2];
            ldsm_x4(bH[0][0], bH[0][1], bH[1][0], bH[1][1], bH_addr + ksb);
            ldsm_x4(bH[2][0], bH[2][1], bH[3][0], bH[3][1], bH_addr + ksb + 16 * 20 * 4);
            ldsm_x4(bL[0][0], bL[0][1], bL[1][0], bL[1][1], bL_addr + ksb);
            ldsm_x4(bL[2][0], bL[2][1], bL[3][0], bL[3][1], bL_addr + ksb + 16 * 20 * 4);
#pragma unroll
            for (int m = 0; m < 4; m++) {
                const uint32_t mb = m * 16 * 20 * 4;
                uint32_t aH[4], aL[4];
                ldsm_x4(aH[0], aH[1], aH[2], aH[3], aH_addr + mb + ksb);
                ldsm_x4(aL[0], aL[1], aL[2], aL[3], aL_addr + mb + ksb);
#pragma unroll
                for (int n = 0; n < 4; n++) {
                    mma_bf16(acc[m][n], aH, bH[n]);
                    mma_bf16(acc[m][n], aH, bL[n]);
                    mma_bf16(acc[m][n], aL, bH[n]);
                }
            }
        }
        __syncthreads();
    }

    // --- epilogue ---
#pragma unroll
    for (int n = 0; n < 4; n++) {
        const int col = n0 + wn + n * 8 + 2 * tig;
        const float b0 = bias[col];
        const float b1 = bias[col + 1];
#pragma unroll
        for (int m = 0; m < 4; m++) {
            const int r0 = wm + m * 16 + g;
            float v00 = acc[m][n][0] + b0;
            float v01 = acc[m][n][1] + b1;
            float v10 = acc[m][n][2] + b0;
            float v11 = acc[m][n][3] + b1;
            if (DO_GELU) {
                v00 = gelu_exact(v00); v01 = gelu_exact(v01);
                v10 = gelu_exact(v10); v11 = gelu_exact(v11);
            }
            if (GROUPED) {
                if (m0 + r0 < rows) {
                    float* p = Cout + (size_t)(segBase + m0 + r0) * N + col;
                    *reinterpret_cast<float2*>(p) = make_float2(v00, v01);
                }
                if (m0 + r0 + 8 < rows) {
                    float* p = Cout + (size_t)(segBase + m0 + r0 + 8) * N + col;
                    *reinterpret_cast<float2*>(p) = make_float2(v10, v11);
                }
            } else {
                float* p0 = Cout + (size_t)(m0 + r0) * N + col;
                float* p1 = Cout + (size_t)(m0 + r0 + 8) * N + col;
                *reinterpret_cast<float2*>(p0) = make_float2(v00, v01);
                *reinterpret_cast<float2*>(p1) = make_float2(v10, v11);
            }
        }
    }
}

// ---------------------------------------------------------------------------
// Routing: one warp per sub-token.
// ---------------------------------------------------------------------------
__global__ void routing_kernel(const float* __restrict__ emb)
{
    const int warp = (blockIdx.x * blockDim.x + threadIdx.x) >> 5;
    const int lane = threadIdx.x & 31;
    if (warp >= NSUB) return;

    const float* trow = g_h + (size_t)warp * HD;
    const float tv0 = trow[lane];
    const float tv1 = trow[lane + 32];
    const float tv2 = trow[lane + 64];
    const float tv3 = trow[lane + 96];

    float logits[NE];
#pragma unroll
    for (int e = 0; e < NE; e++) {
        float p = tv0 * emb[(lane      ) * NE + e]
                + tv1 * emb[(lane + 32 ) * NE + e]
                + tv2 * emb[(lane + 64 ) * NE + e]
                + tv3 * emb[(lane + 96 ) * NE + e];
#pragma unroll
        for (int s = 16; s > 0; s >>= 1) p += __shfl_xor_sync(0xffffffffu, p, s);
        logits[e] = p;
    }

    float mx = logits[0];
#pragma unroll
    for (int e = 1; e < NE; e++) mx = fmaxf(mx, logits[e]);
    float sum = 0.0f;
#pragma unroll
    for (int e = 0; e < NE; e++) { logits[e] = expf(logits[e] - mx); sum += logits[e]; }
    const float inv = 1.0f / sum;

    int i0 = 0; float v0 = logits[0];
#pragma unroll
    for (int e = 1; e < NE; e++) if (logits[e] > v0) { v0 = logits[e]; i0 = e; }
    int i1 = -1; float v1 = -1.0f;
#pragma unroll
    for (int e = 0; e < NE; e++) if (e != i0 && logits[e] > v1) { v1 = logits[e]; i1 = e; }

    if (lane == 0) {
        g_topi[2 * warp + 0] = i0;
        g_topi[2 * warp + 1] = i1;
        g_topw[2 * warp + 0] = v0 * inv;
        g_topw[2 * warp + 1] = v1 * inv;
    }
}

// ---------------------------------------------------------------------------
// Routing bookkeeping
// ---------------------------------------------------------------------------
__global__ void zero_counts() {
    int i = threadIdx.x;
    if (i < NE) { g_counts[i] = 0; g_cursor[i] = 0; }
}
__global__ void hist_kernel() {
    int i = blockIdx.x * blockDim.x + threadIdx.x;
    if (i < NPAIR) atomicAdd(&g_counts[g_topi[i]], 1);
}
__global__ void scan_kernel() {
    int s = 0;
    for (int e = 0; e < NE; e++) { g_offsets[e] = s; s += g_counts[e]; }
    g_offsets[NE] = s;
}
__global__ void scatter_kernel() {
    int i = blockIdx.x * blockDim.x + threadIdx.x;
    if (i < NPAIR) {
        int e = g_topi[i];
        int slot = g_offsets[e] + atomicAdd(&g_cursor[e], 1);
        g_perm[slot] = i >> 1;
        g_pos[i] = slot;
    }
}

// ---------------------------------------------------------------------------
// Combine
// ---------------------------------------------------------------------------
__global__ void combine_kernel() {
    int idx = blockIdx.x * blockDim.x + threadIdx.x;
    int t = idx >> 7;
    int j = idx & 127;
    float w0 = g_topw[2 * t + 0];
    float w1 = g_topw[2 * t + 1];
    int   s0 = g_pos [2 * t + 0];
    int   s1 = g_pos [2 * t + 1];
    g_comb[idx] = w0 * g_eo[(size_t)s0 * HD + j] + w1 * g_eo[(size_t)s1 * HD + j];
}

// ---------------------------------------------------------------------------
// Launch
// ---------------------------------------------------------------------------
extern "C" void kernel_launch(void* const* d_in, const int* in_sizes, int n_in,
                              void* d_out, int out_size)
{
    (void)in_sizes; (void)n_in; (void)out_size;
    const float* x   = (const float*)d_in[0];
    const float* Wm  = (const float*)d_in[1];
    const float* bm  = (const float*)d_in[2];
    const float* emb = (const float*)d_in[3];
    const float* W1  = (const float*)d_in[4];
    const float* b1  = (const float*)d_in[5];
    const float* W2  = (const float*)d_in[6];
    const float* b2  = (const float*)d_in[7];
    const float* Wo  = (const float*)d_in[8];
    const float* bo  = (const float*)d_in[9];
    float* out = (float*)d_out;

    float *h_p, *comb_p, *hmid_p, *eo_p;
    cudaGetSymbolAddress((void**)&h_p,    g_h);
    cudaGetSymbolAddress((void**)&comb_p, g_comb);
    cudaGetSymbolAddress((void**)&hmid_p, g_hmid);
    cudaGetSymbolAddress((void**)&eo_p,   g_eo);
    uint32_t *WmH, *WmL, *W1H, *W1L, *W2H, *W2L, *WoH, *WoL;
    cudaGetSymbolAddress((void**)&WmH, g_WmH); cudaGetSymbolAddress((void**)&WmL, g_WmL);
    cudaGetSymbolAddress((void**)&W1H, g_W1H); cudaGetSymbolAddress((void**)&W1L, g_W1L);
    cudaGetSymbolAddress((void**)&W2H, g_W2H); cudaGetSymbolAddress((void**)&W2L, g_W2L);
    cudaGetSymbolAddress((void**)&WoH, g_WoH); cudaGetSymbolAddress((void**)&WoL, g_WoL);

    // 0) prepack weights (transpose + bf16 hi/lo split)
    prepack_kernel<<<dim3(DIM/32, DIM/64, 1),  256>>>(Wm, WmH, WmL, DIM, DIM);
    prepack_kernel<<<dim3(II/32,  HD/64,  NE), 256>>>(W1, W1H, W1L, HD, II);
    prepack_kernel<<<dim3(HD/32,  II/64,  NE), 256>>>(W2, W2H, W2L, II, HD);
    prepack_kernel<<<dim3(DIM/32, DIM/64, 1),  256>>>(Wo, WoH, WoL, DIM, DIM);

    // 1) h = x @ Wm + bm
    mma_gemm<false,false,false><<<dim3(DIM/128, NTOK/128), 256>>>(
        x, WmH, WmL, bm, h_p, NTOK, DIM, DIM);

    // 2) routing
    routing_kernel<<<NSUB / 8, 256>>>(emb);

    // 3) expert bookkeeping
    zero_counts<<<1, 32>>>();
    hist_kernel<<<NPAIR / 256, 256>>>();
    scan_kernel<<<1, 1>>>();
    scatter_kernel<<<NPAIR / 256, 256>>>();

    // 4) hmid = gelu(t @ W1[e] + b1[e])   K=128, N=512 (gathered A)
    mma_gemm<true,true,true><<<dim3(NPAIR/128, NE, II/128), 256>>>(
        h_p, W1H, W1L, b1, hmid_p, 0, II, HD);

    // 5) eo = hmid @ W2[e] + b2[e]        K=512, N=128
    mma_gemm<true,false,false><<<dim3(NPAIR/128, NE, HD/128), 256>>>(
        hmid_p, W2H, W2L, b2, eo_p, 0, HD, II);

    // 6) combine
    combine_kernel<<<(NSUB * HD) / 256, 256>>>();

    // 7) out = comb @ Wo + bo
    mma_gemm<false,false,false><<<dim3(DIM/128, NTOK/128), 256>>>(
        comb_p, WoH, WoL, bo, out, NTOK, DIM, DIM);
}